// round 4
// baseline (speedup 1.0000x reference)
#include <cuda_runtime.h>
#include <cuda_bf16.h>

#define VOCAB 100000
#define EMBED 256
#define SEQ   8192

struct F8 { float v[8]; };

// 256-bit gather load: non-coherent, bias L2 to retain table rows (they have reuse).
__device__ __forceinline__ F8 ldg256_evict_last(const float* p) {
    F8 r;
    asm("ld.global.nc.L2::evict_last.v8.b32 {%0,%1,%2,%3,%4,%5,%6,%7}, [%8];"
        : "=f"(r.v[0]), "=f"(r.v[1]), "=f"(r.v[2]), "=f"(r.v[3]),
          "=f"(r.v[4]), "=f"(r.v[5]), "=f"(r.v[6]), "=f"(r.v[7])
        : "l"(p));
    return r;
}

// Output store: streaming / evict-first — write-once data must not pollute L2.
__device__ __forceinline__ void stg_streaming(float* p, float a, float b, float c, float d) {
    asm volatile("st.global.cs.v4.f32 [%0], {%1,%2,%3,%4};"
                 :: "l"(p), "f"(a), "f"(b), "f"(c), "f"(d) : "memory");
}

// Warp-uniform hash id computation for one token position.
__device__ __forceinline__ void compute_ids(const int* __restrict__ tokens,
                                            int t, int ids[6]) {
    const int i = t & (SEQ - 1);
    const int x = tokens[t];
    int h = x;
    #pragma unroll
    for (int n = 2; n <= 8; n++) {
        const int j  = n - 1;
        const int bj = (i >= j) ? tokens[t - j] : 0;   // zero-pad before seq start
        h = (h * 257 + bj) % VOCAB;
        if (n >= 3) ids[n - 3] = (i < n - 1) ? x : h;  // raw byte for early positions
    }
}

// Two tokens per warp: 12 independent 32B gathers in flight per lane before
// any consumption, to keep DRAM bank schedulers uniformly fed.
__global__ __launch_bounds__(256) void hash_ngram_kernel(
    const int*   __restrict__ tokens,
    const float* __restrict__ E3, const float* __restrict__ E4,
    const float* __restrict__ E5, const float* __restrict__ E6,
    const float* __restrict__ E7, const float* __restrict__ E8,
    float* __restrict__ out, int total)
{
    const int tid  = threadIdx.x;
    const int warp = tid >> 5;
    const int lane = tid & 31;
    const int t0   = blockIdx.x * 16 + warp * 2;    // first token of the pair
    const int t1   = t0 + 1;
    if (t0 >= total) return;
    const bool has1 = (t1 < total);

    int ids0[6], ids1[6];
    compute_ids(tokens, t0, ids0);
    if (has1) compute_ids(tokens, t1, ids1);
    else {
        #pragma unroll
        for (int k = 0; k < 6; k++) ids1[k] = ids0[k];  // harmless duplicate loads
    }

    const float* tabs[6] = {E3, E4, E5, E6, E7, E8};

    // Issue all 12 gathers back-to-back.
    F8 v0[6], v1[6];
    #pragma unroll
    for (int k = 0; k < 6; k++)
        v0[k] = ldg256_evict_last(tabs[k] + (size_t)ids0[k] * EMBED + lane * 8);
    #pragma unroll
    for (int k = 0; k < 6; k++)
        v1[k] = ldg256_evict_last(tabs[k] + (size_t)ids1[k] * EMBED + lane * 8);

    const float inv6 = 1.0f / 6.0f;

    float a0[8] = {0,0,0,0,0,0,0,0};
    #pragma unroll
    for (int k = 0; k < 6; k++)
        #pragma unroll
        for (int e = 0; e < 8; e++) a0[e] += v0[k].v[e];
    float* o0 = out + (size_t)t0 * EMBED + lane * 8;
    stg_streaming(o0,     a0[0]*inv6, a0[1]*inv6, a0[2]*inv6, a0[3]*inv6);
    stg_streaming(o0 + 4, a0[4]*inv6, a0[5]*inv6, a0[6]*inv6, a0[7]*inv6);

    if (has1) {
        float a1[8] = {0,0,0,0,0,0,0,0};
        #pragma unroll
        for (int k = 0; k < 6; k++)
            #pragma unroll
            for (int e = 0; e < 8; e++) a1[e] += v1[k].v[e];
        float* o1 = out + (size_t)t1 * EMBED + lane * 8;
        stg_streaming(o1,     a1[0]*inv6, a1[1]*inv6, a1[2]*inv6, a1[3]*inv6);
        stg_streaming(o1 + 4, a1[4]*inv6, a1[5]*inv6, a1[6]*inv6, a1[7]*inv6);
    }
}

extern "C" void kernel_launch(void* const* d_in, const int* in_sizes, int n_in,
                              void* d_out, int out_size) {
    const int*   tokens = (const int*)  d_in[0];
    const float* E3     = (const float*)d_in[1];
    const float* E4     = (const float*)d_in[2];
    const float* E5     = (const float*)d_in[3];
    const float* E6     = (const float*)d_in[4];
    const float* E7     = (const float*)d_in[5];
    const float* E8     = (const float*)d_in[6];
    float* out = (float*)d_out;

    const int total  = in_sizes[0];           // B*S tokens
    const int blocks = (total + 15) / 16;     // 16 tokens per 256-thread block
    hash_ngram_kernel<<<blocks, 256>>>(tokens, E3, E4, E5, E6, E7, E8, out, total);
}

// round 5
// speedup vs baseline: 1.0005x; 1.0005x over previous
#include <cuda_runtime.h>
#include <cuda_bf16.h>

#define VOCAB 100000
#define EMBED 256
#define SEQ   8192

struct F8 { float v[8]; };

// 256-bit gather load: non-coherent, bias L2 to retain table rows (they have reuse).
__device__ __forceinline__ F8 ldg256_evict_last(const float* p) {
    F8 r;
    asm("ld.global.nc.L2::evict_last.v8.b32 {%0,%1,%2,%3,%4,%5,%6,%7}, [%8];"
        : "=f"(r.v[0]), "=f"(r.v[1]), "=f"(r.v[2]), "=f"(r.v[3]),
          "=f"(r.v[4]), "=f"(r.v[5]), "=f"(r.v[6]), "=f"(r.v[7])
        : "l"(p));
    return r;
}

// One token per warp. Each lane handles 8 of the 256 embedding dims:
// 6 gathered 32-byte loads, sum, scale, two 16-byte stores (default .wb so
// L2 batches dirty writebacks and minimizes DRAM read/write turnarounds).
__global__ __launch_bounds__(512) void hash_ngram_kernel(
    const int*   __restrict__ tokens,
    const float* __restrict__ E3, const float* __restrict__ E4,
    const float* __restrict__ E5, const float* __restrict__ E6,
    const float* __restrict__ E7, const float* __restrict__ E8,
    float* __restrict__ out, int total)
{
    const int tid  = threadIdx.x;
    const int t    = blockIdx.x * 16 + (tid >> 5);  // token index in [0, B*S)
    if (t >= total) return;
    const int lane = tid & 31;                      // which 8-float chunk of the row
    const int i    = t & (SEQ - 1);                 // position within sequence

    // Rolling polynomial hash, incremental across n.
    // h_n(i) = (h_{n-1}(i) * 257 + b[i-(n-1)]) % VOCAB, h_1 = b[i].
    const int x = tokens[t];
    int ids[6];
    int h = x;
    #pragma unroll
    for (int n = 2; n <= 8; n++) {
        const int j  = n - 1;
        const int bj = (i >= j) ? tokens[t - j] : 0;   // zero-pad before seq start
        h = (h * 257 + bj) % VOCAB;
        if (n >= 3) ids[n - 3] = (i < n - 1) ? x : h;  // raw byte for early positions
    }

    const float* tabs[6] = {E3, E4, E5, E6, E7, E8};
    float acc[8] = {0.f, 0.f, 0.f, 0.f, 0.f, 0.f, 0.f, 0.f};
    #pragma unroll
    for (int k = 0; k < 6; k++) {
        const F8 v = ldg256_evict_last(tabs[k] + (size_t)ids[k] * EMBED + lane * 8);
        #pragma unroll
        for (int e = 0; e < 8; e++) acc[e] += v.v[e];
    }
    const float inv6 = 1.0f / 6.0f;
    #pragma unroll
    for (int e = 0; e < 8; e++) acc[e] *= inv6;

    float4* o = reinterpret_cast<float4*>(out + (size_t)t * EMBED + lane * 8);
    o[0] = make_float4(acc[0], acc[1], acc[2], acc[3]);
    o[1] = make_float4(acc[4], acc[5], acc[6], acc[7]);
}

extern "C" void kernel_launch(void* const* d_in, const int* in_sizes, int n_in,
                              void* d_out, int out_size) {
    const int*   tokens = (const int*)  d_in[0];
    const float* E3     = (const float*)d_in[1];
    const float* E4     = (const float*)d_in[2];
    const float* E5     = (const float*)d_in[3];
    const float* E6     = (const float*)d_in[4];
    const float* E7     = (const float*)d_in[5];
    const float* E8     = (const float*)d_in[6];
    float* out = (float*)d_out;

    const int total  = in_sizes[0];           // B*S tokens
    const int blocks = (total + 15) / 16;     // 16 tokens per 512-thread block
    hash_ngram_kernel<<<blocks, 512>>>(tokens, E3, E4, E5, E6, E7, E8, out, total);
}